// round 15
// baseline (speedup 1.0000x reference)
#include <cuda_runtime.h>

// Problem constants (fixed by the dataset)
#define NN 100000
#define EE 1600000

// Scratch: __device__ globals only, referenced ONLY from device code
// (host-side symbol use binds the ATS-dereferenceable host shadow -> R2 bug).
__device__ int   g_is64;
__device__ int   g_deg[NN];
__device__ int   g_off[NN];
__device__ int   g_cur[NN];
__device__ int   g_csr[EE];
__device__ int   g_bsum[1024];
__device__ float g_t1[NN * 32];
__device__ float g_a1[NN * 32];
__device__ float g_t2[NN * 48];
__device__ float g_a2[NN * 48];
__device__ float g_t3[NN * 16];

// Packed fp32x2 helpers (Blackwell FFMA2 — exact fp32, 2 FMAs/inst)
__device__ __forceinline__ unsigned long long fma2(
    unsigned long long a, unsigned long long b, unsigned long long c) {
    unsigned long long d;
    asm("fma.rn.f32x2 %0, %1, %2, %3;" : "=l"(d) : "l"(a), "l"(b), "l"(c));
    return d;
}
__device__ __forceinline__ unsigned long long add2(
    unsigned long long a, unsigned long long b) {
    unsigned long long d;
    asm("add.rn.f32x2 %0, %1, %2;" : "=l"(d) : "l"(a), "l"(b));
    return d;
}
__device__ __forceinline__ unsigned long long bcast2(float v) {
    unsigned long long d;
    asm("mov.b64 %0, {%1, %1};" : "=l"(d) : "f"(v));
    return d;
}

// ---------------------------------------------------------------------------
// CSR build (side stream, hidden behind node1)
// ---------------------------------------------------------------------------
__global__ __launch_bounds__(256) void k_init(const void* __restrict__ ei, int N) {
    int i = blockIdx.x * blockDim.x + threadIdx.x;
    if (i < N) g_deg[i] = 0;
    if (i == 0) {
        const long long* p = (const long long*)ei;
        int ok = 1;
        for (int q = 0; q < 64; q++) {
            long long v = p[q];
            if (v < 0 || v >= (long long)N) { ok = 0; break; }
        }
        g_is64 = ok;
    }
}

__global__ __launch_bounds__(256) void k_hist(const void* __restrict__ ei, int E) {
    int i = blockIdx.x * blockDim.x + threadIdx.x;
    if (i >= E) return;
    int d;
    if (g_is64) d = (int)((const long long*)ei)[E + i];
    else        d = ((const int*)ei)[E + i];
    atomicAdd(&g_deg[d], 1);
}

__global__ __launch_bounds__(256) void k_scanA(int N) {
    __shared__ int s[256];
    int b = blockIdx.x, t = threadIdx.x;
    int base = b * 1024 + t * 4;
    int sum = 0;
#pragma unroll
    for (int i = 0; i < 4; i++) {
        int idx = base + i;
        if (idx < N) sum += g_deg[idx];
    }
    s[t] = sum;
    __syncthreads();
#pragma unroll
    for (int d = 128; d > 0; d >>= 1) {
        if (t < d) s[t] += s[t + d];
        __syncthreads();
    }
    if (t == 0) g_bsum[b] = s[0];
}

__global__ __launch_bounds__(256) void k_scanC(int N, int NB) {
    __shared__ int sb_[128];
    __shared__ int s[256];
    int b = blockIdx.x, t = threadIdx.x;
    if (t < 128) sb_[t] = (t < NB) ? g_bsum[t] : 0;
    __syncthreads();
#pragma unroll
    for (int d = 1; d < 128; d <<= 1) {
        int x = (t >= d && t < 128) ? sb_[t - d] : 0;
        __syncthreads();
        if (t < 128) sb_[t] += x;
        __syncthreads();
    }
    int boff = (b == 0) ? 0 : sb_[b - 1];

    int base = b * 1024 + t * 4;
    int v[4];
    int sum = 0;
#pragma unroll
    for (int i = 0; i < 4; i++) {
        int idx = base + i;
        v[i] = (idx < N) ? g_deg[idx] : 0;
        sum += v[i];
    }
    s[t] = sum;
    __syncthreads();
    for (int d = 1; d < 256; d <<= 1) {
        int x = (t >= d) ? s[t - d] : 0;
        __syncthreads();
        s[t] += x;
        __syncthreads();
    }
    int run = s[t] - sum + boff;
#pragma unroll
    for (int i = 0; i < 4; i++) {
        int idx = base + i;
        if (idx < N) {
            g_off[idx] = run;
            g_cur[idx] = run;
            run += v[i];
        }
    }
}

__global__ __launch_bounds__(256) void k_scatter(const void* __restrict__ ei, int E) {
    int i = blockIdx.x * blockDim.x + threadIdx.x;
    if (i >= E) return;
    int s, d;
    if (g_is64) {
        const long long* p = (const long long*)ei;
        s = (int)p[i];
        d = (int)p[E + i];
    } else {
        const int* p = (const int*)ei;
        s = p[i];
        d = p[E + i];
    }
    int pos = atomicAdd(&g_cur[d], 1);
    g_csr[pos] = s;
}

// ---------------------------------------------------------------------------
// Dual-GEMM j-tile body, FFMA2 (weights/bias from smem)
// ---------------------------------------------------------------------------
#define JTILE_BODY2(IN, OUT)                                                   \
    unsigned long long at2[4], ar2[4];                                         \
    {                                                                          \
        ulonglong2 binit0 = *(const ulonglong2*)&sb[jt];                       \
        ulonglong2 binit1 = *(const ulonglong2*)&sb[jt + 4];                   \
        at2[0] = 0ull; at2[1] = 0ull; at2[2] = 0ull; at2[3] = 0ull;            \
        ar2[0] = binit0.x; ar2[1] = binit0.y;                                  \
        ar2[2] = binit1.x; ar2[3] = binit1.y;                                  \
    }                                                                          \
    _Pragma("unroll")                                                          \
    for (int k = 0; k < IN; k++) {                                             \
        unsigned long long hk2 = bcast2(h[k]);                                 \
        ulonglong2 wr01 = *(const ulonglong2*)&sWr[k * OUT + jt];              \
        ulonglong2 wr23 = *(const ulonglong2*)&sWr[k * OUT + jt + 4];          \
        ulonglong2 wo01 = *(const ulonglong2*)&sWo[k * OUT + jt];              \
        ulonglong2 wo23 = *(const ulonglong2*)&sWo[k * OUT + jt + 4];          \
        at2[0] = fma2(hk2, wr01.x, at2[0]);                                    \
        at2[1] = fma2(hk2, wr01.y, at2[1]);                                    \
        at2[2] = fma2(hk2, wr23.x, at2[2]);                                    \
        at2[3] = fma2(hk2, wr23.y, at2[3]);                                    \
        ar2[0] = fma2(hk2, wo01.x, ar2[0]);                                    \
        ar2[1] = fma2(hk2, wo01.y, ar2[1]);                                    \
        ar2[2] = fma2(hk2, wo23.x, ar2[2]);                                    \
        ar2[3] = fma2(hk2, wo23.y, ar2[3]);                                    \
    }

// ---------------------------------------------------------------------------
// K1: layer 1 node kernel. h0 = concat(x[48], ax[16]) -> 64
// ---------------------------------------------------------------------------
__global__ __launch_bounds__(256) void k_node1(
    const float* __restrict__ x, const float* __restrict__ ax,
    const float* __restrict__ Wrel, const float* __restrict__ Wroot,
    const float* __restrict__ b, int N)
{
    __shared__ __align__(16) float sWr[64 * 32];
    __shared__ __align__(16) float sWo[64 * 32];
    __shared__ __align__(16) float sb[32];
    for (int t = threadIdx.x; t < 64 * 32; t += 256) { sWr[t] = Wrel[t]; sWo[t] = Wroot[t]; }
    if (threadIdx.x < 32) sb[threadIdx.x] = b[threadIdx.x];
    __syncthreads();

    int i = blockIdx.x * 256 + threadIdx.x;
    if (i >= N) return;

    float h[64];
    const float4* xp = (const float4*)(x + (size_t)i * 48);
#pragma unroll
    for (int q = 0; q < 12; q++) {
        float4 v = xp[q];
        h[4*q] = v.x; h[4*q+1] = v.y; h[4*q+2] = v.z; h[4*q+3] = v.w;
    }
    const float4* ap = (const float4*)(ax + (size_t)i * 16);
#pragma unroll
    for (int q = 0; q < 4; q++) {
        float4 v = ap[q];
        h[48+4*q] = v.x; h[48+4*q+1] = v.y; h[48+4*q+2] = v.z; h[48+4*q+3] = v.w;
    }

    float* t1 = g_t1 + (size_t)i * 32;
    float* a1 = g_a1 + (size_t)i * 32;
#pragma unroll 1
    for (int jt = 0; jt < 32; jt += 8) {
        JTILE_BODY2(64, 32)
        *(ulonglong2*)&t1[jt]     = make_ulonglong2(at2[0], at2[1]);
        *(ulonglong2*)&t1[jt + 4] = make_ulonglong2(at2[2], at2[3]);
        *(ulonglong2*)&a1[jt]     = make_ulonglong2(ar2[0], ar2[1]);
        *(ulonglong2*)&a1[jt + 4] = make_ulonglong2(ar2[2], ar2[3]);
    }
}

// ---------------------------------------------------------------------------
// K3: layer 2 node kernel (sliced: nodes [nStart, nStart+nCount))
// ---------------------------------------------------------------------------
__global__ __launch_bounds__(256) void k_node2(
    const float* __restrict__ lf,
    const float* __restrict__ Wrel, const float* __restrict__ Wroot,
    const float* __restrict__ b, int nStart, int nCount, int N)
{
    __shared__ __align__(16) float sWr[48 * 48];
    __shared__ __align__(16) float sWo[48 * 48];
    __shared__ __align__(16) float sb[48];
    for (int t = threadIdx.x; t < 48 * 48; t += 256) { sWr[t] = Wrel[t]; sWo[t] = Wroot[t]; }
    if (threadIdx.x < 48) sb[threadIdx.x] = b[threadIdx.x];
    __syncthreads();

    int li = blockIdx.x * 256 + threadIdx.x;
    if (li >= nCount) return;
    int i = nStart + li;
    if (i >= N) return;

    float h[48];
    const float4* a1p = (const float4*)(g_a1 + (size_t)i * 32);
#pragma unroll
    for (int q = 0; q < 8; q++) {
        float4 v = a1p[q];
        h[4*q]   = fmaxf(v.x, 0.0f);
        h[4*q+1] = fmaxf(v.y, 0.0f);
        h[4*q+2] = fmaxf(v.z, 0.0f);
        h[4*q+3] = fmaxf(v.w, 0.0f);
    }
    const float4* lp = (const float4*)(lf + (size_t)i * 16);
#pragma unroll
    for (int q = 0; q < 4; q++) {
        float4 v = lp[q];
        h[32+4*q] = v.x; h[32+4*q+1] = v.y; h[32+4*q+2] = v.z; h[32+4*q+3] = v.w;
    }

    float* t2 = g_t2 + (size_t)i * 48;
    float* a2 = g_a2 + (size_t)i * 48;
#pragma unroll 1
    for (int jt = 0; jt < 48; jt += 8) {
        JTILE_BODY2(48, 48)
        *(ulonglong2*)&t2[jt]     = make_ulonglong2(at2[0], at2[1]);
        *(ulonglong2*)&t2[jt + 4] = make_ulonglong2(at2[2], at2[3]);
        *(ulonglong2*)&a2[jt]     = make_ulonglong2(ar2[0], ar2[1]);
        *(ulonglong2*)&a2[jt + 4] = make_ulonglong2(ar2[2], ar2[3]);
    }
}

// ---------------------------------------------------------------------------
// K5: layer 3 node kernel (sliced)
// ---------------------------------------------------------------------------
__global__ __launch_bounds__(256) void k_node3(
    const float* __restrict__ ax,
    const float* __restrict__ Wrel, const float* __restrict__ Wroot,
    const float* __restrict__ b, float* __restrict__ out,
    int nStart, int nCount, int N)
{
    __shared__ __align__(16) float sWr[48 * 16];
    __shared__ __align__(16) float sWo[48 * 16];
    __shared__ __align__(16) float sb[16];
    for (int t = threadIdx.x; t < 48 * 16; t += 256) { sWr[t] = Wrel[t]; sWo[t] = Wroot[t]; }
    if (threadIdx.x < 16) sb[threadIdx.x] = b[threadIdx.x];
    __syncthreads();

    int li = blockIdx.x * 256 + threadIdx.x;
    if (li >= nCount) return;
    int i = nStart + li;
    if (i >= N) return;

    float h[48];
    const float4* a2p = (const float4*)(g_a2 + (size_t)i * 48);
#pragma unroll
    for (int q = 0; q < 12; q++) {
        float4 v = a2p[q];
        h[4*q]   = fmaxf(v.x, 0.0f);
        h[4*q+1] = fmaxf(v.y, 0.0f);
        h[4*q+2] = fmaxf(v.z, 0.0f);
        h[4*q+3] = fmaxf(v.w, 0.0f);
    }

    const ulonglong2* axp = (const ulonglong2*)(ax + (size_t)i * 16);
    float* t3 = g_t3 + (size_t)i * 16;
    float* o  = out + (size_t)i * 16;
#pragma unroll 1
    for (int jt = 0; jt < 16; jt += 8) {
        JTILE_BODY2(48, 16)
        ulonglong2 av0 = axp[jt / 4];
        ulonglong2 av1 = axp[jt / 4 + 1];
        *(ulonglong2*)&t3[jt]     = make_ulonglong2(at2[0], at2[1]);
        *(ulonglong2*)&t3[jt + 4] = make_ulonglong2(at2[2], at2[3]);
        *(ulonglong2*)&o[jt]      = make_ulonglong2(add2(ar2[0], av0.x),
                                                    add2(ar2[1], av0.y));
        *(ulonglong2*)&o[jt + 4]  = make_ulonglong2(add2(ar2[2], av1.x),
                                                    add2(ar2[3], av1.y));
    }
}

// ---------------------------------------------------------------------------
// CSR aggregation (sliced): thread (node, chunk), unroll-8 neighbors.
// ---------------------------------------------------------------------------
template <int CH>
__device__ __forceinline__ void agg_body(
    const float* __restrict__ t, float* __restrict__ acc,
    int nStart, int nCount, int N)
{
    int tid = blockIdx.x * blockDim.x + threadIdx.x;
    if (tid >= nCount * CH) return;
    int n = nStart + tid / CH;
    if (n >= N) return;
    int c = tid % CH;

    int beg = g_off[n];
    int end = beg + g_deg[n];

    float4 a0 = make_float4(0.f,0.f,0.f,0.f);
    float4 a1 = make_float4(0.f,0.f,0.f,0.f);
    float4 a2 = make_float4(0.f,0.f,0.f,0.f);
    float4 a3 = make_float4(0.f,0.f,0.f,0.f);

    int j = beg;
    for (; j + 7 < end; j += 8) {
        int s0 = g_csr[j],   s1 = g_csr[j+1], s2 = g_csr[j+2], s3 = g_csr[j+3];
        int s4 = g_csr[j+4], s5 = g_csr[j+5], s6 = g_csr[j+6], s7 = g_csr[j+7];
        float4 v0 = *(const float4*)(t + (size_t)s0 * (CH*4) + c*4);
        float4 v1 = *(const float4*)(t + (size_t)s1 * (CH*4) + c*4);
        float4 v2 = *(const float4*)(t + (size_t)s2 * (CH*4) + c*4);
        float4 v3 = *(const float4*)(t + (size_t)s3 * (CH*4) + c*4);
        float4 v4 = *(const float4*)(t + (size_t)s4 * (CH*4) + c*4);
        float4 v5 = *(const float4*)(t + (size_t)s5 * (CH*4) + c*4);
        float4 v6 = *(const float4*)(t + (size_t)s6 * (CH*4) + c*4);
        float4 v7 = *(const float4*)(t + (size_t)s7 * (CH*4) + c*4);
        a0.x += v0.x + v4.x; a0.y += v0.y + v4.y; a0.z += v0.z + v4.z; a0.w += v0.w + v4.w;
        a1.x += v1.x + v5.x; a1.y += v1.y + v5.y; a1.z += v1.z + v5.z; a1.w += v1.w + v5.w;
        a2.x += v2.x + v6.x; a2.y += v2.y + v6.y; a2.z += v2.z + v6.z; a2.w += v2.w + v6.w;
        a3.x += v3.x + v7.x; a3.y += v3.y + v7.y; a3.z += v3.z + v7.z; a3.w += v3.w + v7.w;
    }
    for (; j + 1 < end; j += 2) {
        int s0 = g_csr[j], s1 = g_csr[j+1];
        float4 v0 = *(const float4*)(t + (size_t)s0 * (CH*4) + c*4);
        float4 v1 = *(const float4*)(t + (size_t)s1 * (CH*4) + c*4);
        a0.x += v0.x; a0.y += v0.y; a0.z += v0.z; a0.w += v0.w;
        a1.x += v1.x; a1.y += v1.y; a1.z += v1.z; a1.w += v1.w;
    }
    if (j < end) {
        int s = g_csr[j];
        float4 v = *(const float4*)(t + (size_t)s * (CH*4) + c*4);
        a0.x += v.x; a0.y += v.y; a0.z += v.z; a0.w += v.w;
    }

    float* ap = acc + (size_t)n * (CH*4) + c*4;
    float4 cur = *(float4*)ap;
    *(float4*)ap = make_float4(cur.x + a0.x + a1.x + a2.x + a3.x,
                               cur.y + a0.y + a1.y + a2.y + a3.y,
                               cur.z + a0.z + a1.z + a2.z + a3.z,
                               cur.w + a0.w + a1.w + a2.w + a3.w);
}

__global__ __launch_bounds__(256) void k_agg1(int nStart, int nCount, int N) {
    agg_body<8>(g_t1, g_a1, nStart, nCount, N);
}
__global__ __launch_bounds__(256) void k_agg2(int nStart, int nCount, int N) {
    agg_body<12>(g_t2, g_a2, nStart, nCount, N);
}
__global__ __launch_bounds__(256) void k_agg3(float* __restrict__ out, int N) {
    agg_body<4>(g_t3, out, 0, N, N);
}

// ---------------------------------------------------------------------------
// kernel_launch: CSR ‖ node1; then per layer, agg slices on s2 pipelined with
// node slices on the main stream (agg_k slice s -> node_{k+1} slice s).
// ---------------------------------------------------------------------------
#define NSLICE 4

extern "C" void kernel_launch(void* const* d_in, const int* in_sizes, int n_in,
                              void* d_out, int out_size)
{
    const float* x   = (const float*)d_in[0];
    const void*  ei  = d_in[1];
    const float* ax  = (const float*)d_in[2];
    const float* lf  = (const float*)d_in[3];
    const float* W1r = (const float*)d_in[4];
    const float* b1  = (const float*)d_in[5];
    const float* W1o = (const float*)d_in[6];
    const float* W2r = (const float*)d_in[7];
    const float* b2  = (const float*)d_in[8];
    const float* W2o = (const float*)d_in[9];
    const float* W3r = (const float*)d_in[10];
    const float* b3  = (const float*)d_in[11];
    const float* W3o = (const float*)d_in[12];
    float* out = (float*)d_out;

    const int N = in_sizes[0] / 48;
    const int E = in_sizes[1] / 2;

    const int TB = 256;
    const int nodeBlocks = (N + TB - 1) / TB;
    const int edgeBlocks = (E + TB - 1) / TB;
    const int NB = (N + 1023) / 1024;

    // slice geometry (multiple of 256)
    int slice = ((N + NSLICE - 1) / NSLICE + 255) & ~255;

    static cudaStream_t s2 = nullptr;
    static cudaEvent_t evFork = nullptr, evT1 = nullptr, evT2 = nullptr;
    static cudaEvent_t evA[NSLICE], evB[NSLICE];
    if (!s2) {
        cudaStreamCreateWithFlags(&s2, cudaStreamNonBlocking);
        cudaEventCreateWithFlags(&evFork, cudaEventDisableTiming);
        cudaEventCreateWithFlags(&evT1, cudaEventDisableTiming);
        cudaEventCreateWithFlags(&evT2, cudaEventDisableTiming);
        for (int s = 0; s < NSLICE; s++) {
            cudaEventCreateWithFlags(&evA[s], cudaEventDisableTiming);
            cudaEventCreateWithFlags(&evB[s], cudaEventDisableTiming);
        }
    }

    // Fork: CSR build on s2, node1 on the main (capture) stream.
    cudaEventRecord(evFork, 0);
    cudaStreamWaitEvent(s2, evFork, 0);

    k_init   <<<nodeBlocks, TB, 0, s2>>>(ei, N);
    k_hist   <<<edgeBlocks, TB, 0, s2>>>(ei, E);
    k_scanA  <<<NB, TB, 0, s2>>>(N);
    k_scanC  <<<NB, TB, 0, s2>>>(N, NB);
    k_scatter<<<edgeBlocks, TB, 0, s2>>>(ei, E);

    // node1 on main, concurrent with CSR build; s2 then waits for t1.
    k_node1<<<nodeBlocks, TB>>>(x, ax, W1r, W1o, b1, N);
    cudaEventRecord(evT1, 0);
    cudaStreamWaitEvent(s2, evT1, 0);

    // ---- Layer 1->2 pipeline: agg1 slices (s2) feed node2 slices (main) ----
    for (int s = 0; s < NSLICE; s++) {
        int st = s * slice;
        int cnt = N - st; if (cnt > slice) cnt = slice; if (cnt < 0) cnt = 0;
        int blks = (cnt * 8 + TB - 1) / TB; if (blks < 1) blks = 1;
        k_agg1<<<blks, TB, 0, s2>>>(st, cnt, N);
        cudaEventRecord(evA[s], s2);
    }
    for (int s = 0; s < NSLICE; s++) {
        int st = s * slice;
        int cnt = N - st; if (cnt > slice) cnt = slice; if (cnt < 0) cnt = 0;
        int blks = (cnt + TB - 1) / TB; if (blks < 1) blks = 1;
        cudaStreamWaitEvent(0, evA[s], 0);
        k_node2<<<blks, TB>>>(lf, W2r, W2o, b2, st, cnt, N);
    }
    cudaEventRecord(evT2, 0);
    cudaStreamWaitEvent(s2, evT2, 0);

    // ---- Layer 2->3 pipeline ----
    for (int s = 0; s < NSLICE; s++) {
        int st = s * slice;
        int cnt = N - st; if (cnt > slice) cnt = slice; if (cnt < 0) cnt = 0;
        int blks = (cnt * 12 + TB - 1) / TB; if (blks < 1) blks = 1;
        k_agg2<<<blks, TB, 0, s2>>>(st, cnt, N);
        cudaEventRecord(evB[s], s2);
    }
    for (int s = 0; s < NSLICE; s++) {
        int st = s * slice;
        int cnt = N - st; if (cnt > slice) cnt = slice; if (cnt < 0) cnt = 0;
        int blks = (cnt + TB - 1) / TB; if (blks < 1) blks = 1;
        cudaStreamWaitEvent(0, evB[s], 0);
        k_node3<<<blks, TB>>>(ax, W3r, W3o, b3, out, st, cnt, N);
    }

    // Final aggregation into d_out (needs all t3; main-stream ordered).
    k_agg3<<<((long long)N * 4 + TB - 1) / TB, TB>>>(out, N);
}